// round 7
// baseline (speedup 1.0000x reference)
#include <cuda_runtime.h>
#include <math.h>
#include <stdint.h>

#define T_TOK 8192
#define D_DIM 1024
#define F_DIM 4096
#define E_NUM 8
#define A_TOT (2 * T_TOK)      /* 16384 real (token, expert) assignments */
#define A_PAD 17408            /* A_TOT + 8*128 padding, multiple of 128 */
#define NMT   (A_PAD / 128)    /* 136 global 128-row M-slabs */
#define NCH1  (D_DIM / 16)     /* 64 K-chunks, GEMM1 */
#define NCH2  (F_DIM / 16)     /* 256 K-chunks, GEMM2 */
#define NT1   (F_DIM / 128)    /* 32 N-tiles, GEMM1 */
#define NT2   (D_DIM / 128)    /* 8 N-tiles, GEMM2 */

// ---------------- scratch (no allocation allowed -> device globals) --------
__device__ int   g_counts[E_NUM];
__device__ int   g_offsets[E_NUM + 1];          // PADDED offsets (mult of 128)
__device__ int   g_expidx[A_TOT];
__device__ int   g_pos[A_TOT];
__device__ float g_wt[A_TOT];
__device__ int   g_slot[A_TOT];
__device__ int   g_sorted_tok[A_PAD];
__device__ float g_sorted_wt[A_PAD];
// Fragment-major buffers: slab = 2048 floats (16 blocks x 32 lanes x 4).
__device__ float g_xa[(size_t)NMT * NCH1 * 2048];           //  68 MB A-frags GEMM1
__device__ float g_hf[(size_t)NMT * NCH2 * 2048];           // 285 MB A-frags GEMM2 (tf32 h)
__device__ float g_w1f[(size_t)E_NUM * NT1 * NCH1 * 2048];  // 128 MB B-frags GEMM1
__device__ float g_w2f[(size_t)E_NUM * NT2 * NCH2 * 2048];  // 128 MB B-frags GEMM2
__device__ float g_y[(size_t)A_PAD * D_DIM];                //  71 MB per-assignment outputs

__device__ __forceinline__ float to_tf32(float v) {
    float r;
    asm("cvt.rna.tf32.f32 %0, %1;" : "=f"(r) : "f"(v));
    return r;
}

__device__ __forceinline__ float gelu_exact(float v) {
    return 0.5f * v * (1.0f + erff(v * 0.70710678118654752440f));
}

__device__ __forceinline__ uint32_t smem_u32(const void* p) {
    uint32_t a;
    asm("{ .reg .u64 t; cvta.to.shared.u64 t, %1; cvt.u32.u64 %0, t; }"
        : "=r"(a) : "l"(p));
    return a;
}

// m16n8k8 tf32 mma: C[16x8] += A[16x8] * B[8x8]
__device__ __forceinline__ void mma_tf32(float* c, const uint32_t* a,
                                         uint32_t b0, uint32_t b1) {
    asm volatile(
        "mma.sync.aligned.m16n8k8.row.col.f32.tf32.tf32.f32 "
        "{%0,%1,%2,%3}, {%4,%5,%6,%7}, {%8,%9}, {%0,%1,%2,%3};"
        : "+f"(c[0]), "+f"(c[1]), "+f"(c[2]), "+f"(c[3])
        : "r"(a[0]), "r"(a[1]), "r"(a[2]), "r"(a[3]), "r"(b0), "r"(b1));
}

#define CP16(dst_u32, src_ptr) \
    asm volatile("cp.async.cg.shared.global [%0], [%1], 16;" \
                 :: "r"(dst_u32), "l"(src_ptr))
#define CP_COMMIT() asm volatile("cp.async.commit_group;" ::: "memory")
#define CP_WAIT2()  asm volatile("cp.async.wait_group 2;" ::: "memory")

// ---------------------------------------------------------------------------
__global__ void zero_kernel() {
    if (threadIdx.x < E_NUM) g_counts[threadIdx.x] = 0;
}

__global__ __launch_bounds__(256) void gate_kernel(const float* __restrict__ x,
                                                   const float* __restrict__ gw) {
    __shared__ float red[256][9];
    const int t = blockIdx.x;
    const int tid = threadIdx.x;
    float acc[8] = {0.f, 0.f, 0.f, 0.f, 0.f, 0.f, 0.f, 0.f};
    const float* xr = x + (size_t)t * D_DIM;
    for (int j = tid; j < D_DIM; j += 256) {
        float xv = xr[j];
        const float* g = gw + j * E_NUM;
#pragma unroll
        for (int e = 0; e < 8; e++) acc[e] += xv * g[e];
    }
#pragma unroll
    for (int e = 0; e < 8; e++) red[tid][e] = acc[e];
    __syncthreads();
    for (int s = 128; s > 0; s >>= 1) {
        if (tid < s) {
#pragma unroll
            for (int e = 0; e < 8; e++) red[tid][e] += red[tid + s][e];
        }
        __syncthreads();
    }
    if (tid == 0) {
        float v[8];
#pragma unroll
        for (int e = 0; e < 8; e++) v[e] = red[0][e];
        int i0 = 0;
#pragma unroll
        for (int e = 1; e < 8; e++) if (v[e] > v[i0]) i0 = e;
        int i1 = (i0 == 0) ? 1 : 0;
#pragma unroll
        for (int e = 0; e < 8; e++) if (e != i1 && e != i0 && v[e] > v[i1]) i1 = e;
        float e1 = expf(v[i1] - v[i0]);
        float inv = 1.0f / (1.0f + e1);
        int p0 = atomicAdd(&g_counts[i0], 1);
        int p1 = atomicAdd(&g_counts[i1], 1);
        g_expidx[2 * t + 0] = i0;
        g_expidx[2 * t + 1] = i1;
        g_pos[2 * t + 0] = p0;
        g_pos[2 * t + 1] = p1;
        g_wt[2 * t + 0] = inv;
        g_wt[2 * t + 1] = e1 * inv;
    }
}

__global__ void scan_kernel() {
    if (threadIdx.x == 0) {
        int s = 0;
#pragma unroll
        for (int e = 0; e < E_NUM; e++) {
            g_offsets[e] = s;
            s += (g_counts[e] + 127) & ~127;   // pad each expert to 128
        }
        g_offsets[E_NUM] = s;
    }
}

__global__ void scatter_kernel() {
    int i = blockIdx.x * 256 + threadIdx.x;
    if (i >= A_TOT) return;
    int e = g_expidx[i];
    int s = g_offsets[e] + g_pos[i];
    g_slot[i] = s;
    g_sorted_tok[s] = i >> 1;
    g_sorted_wt[s] = g_wt[i];
}

// Fill padding slots with tok=0, wt=0.
__global__ void pad_fill_kernel() {
    int s = blockIdx.x * 256 + threadIdx.x;
    if (s >= A_PAD) return;
    int e = 0;
#pragma unroll
    for (int i = 1; i < E_NUM; i++) if (s >= g_offsets[i]) e = i;
    int local = s - g_offsets[e];
    if (local >= g_counts[e]) {
        g_sorted_tok[s] = 0;
        g_sorted_wt[s] = 0.0f;
    }
}

// ---------------- fragment pre-format kernels -------------------------------
// Gather routed x rows into A-fragment slabs (tf32-rounded).
__global__ __launch_bounds__(256) void xfrag_kernel(const float* __restrict__ x) {
    const int ch = blockIdx.x;
    const int mt = blockIdx.y;
    __shared__ float sx[128 * 20];
    __shared__ int toks[128];
    const int tid = threadIdx.x;
    if (tid < 128) toks[tid] = g_sorted_tok[mt * 128 + tid];
    __syncthreads();
#pragma unroll
    for (int p = 0; p < 2; p++) {
        int q = tid + p * 256;
        int row = q >> 2, kq = q & 3;
        float4 v = *(const float4*)(x + (size_t)toks[row] * D_DIM + ch * 16 + kq * 4);
        v.x = to_tf32(v.x); v.y = to_tf32(v.y); v.z = to_tf32(v.z); v.w = to_tf32(v.w);
        *(float4*)&sx[row * 20 + kq * 4] = v;
    }
    __syncthreads();
    float* dst = g_xa + ((size_t)mt * NCH1 + ch) * 2048;
#pragma unroll
    for (int p = 0; p < 2; p++) {
        int q = tid + p * 256;
        int blkid = q >> 5, slot = q & 31;
        int mb = blkid >> 1, us = blkid & 1;
        int sg = slot >> 2, t = slot & 3;
        int r0 = mb * 16 + sg, k0 = us * 8 + t;
        float4 v;
        v.x = sx[r0 * 20 + k0];
        v.y = sx[(r0 + 8) * 20 + k0];
        v.z = sx[r0 * 20 + k0 + 4];
        v.w = sx[(r0 + 8) * 20 + k0 + 4];
        *(float4*)&dst[q * 4] = v;
    }
}

// Reformat weights [e][K][N] row-major -> B-fragment slabs (tf32-rounded).
__global__ __launch_bounds__(256) void wfrag_kernel(const float* __restrict__ w,
                                                    float* __restrict__ dstbase,
                                                    int Ndim) {
    const int nt = blockIdx.x;
    const int ch = blockIdx.y;
    const int e = blockIdx.z;
    const int Kdim = gridDim.y * 16;
    __shared__ float s[16 * 132];
    const float* src = w + (size_t)e * Kdim * Ndim + (size_t)(ch * 16) * Ndim + nt * 128;
    const int tid = threadIdx.x;
#pragma unroll
    for (int p = 0; p < 2; p++) {
        int q = tid + p * 256;
        int kk = q >> 5, nn = q & 31;
        float4 v = *(const float4*)(src + (size_t)kk * Ndim + nn * 4);
        v.x = to_tf32(v.x); v.y = to_tf32(v.y); v.z = to_tf32(v.z); v.w = to_tf32(v.w);
        *(float4*)&s[kk * 132 + nn * 4] = v;
    }
    __syncthreads();
    float* dst = dstbase + (((size_t)e * gridDim.x + nt) * gridDim.y + ch) * 2048;
#pragma unroll
    for (int p = 0; p < 2; p++) {
        int q = tid + p * 256;
        int blkid = q >> 5, slot = q & 31;
        int pb = blkid >> 1, us = blkid & 1;
        int sg = slot >> 2, t = slot & 3;
        int n0 = pb * 16 + sg, k0 = us * 8 + t;
        float4 v;
        v.x = s[k0 * 132 + n0];
        v.y = s[(k0 + 4) * 132 + n0];
        v.z = s[k0 * 132 + n0 + 8];
        v.w = s[(k0 + 4) * 132 + n0 + 8];
        *(float4*)&dst[q * 4] = v;
    }
}

// ---------------- mma.sync tf32 grouped GEMM --------------------------------
// CTA 256(M) x 128(N), 8 warps as 4(M) x 2(N), warp tile 64x64.
// A = two 128-row fragment slabs per chunk, B = one slab.
// cp.async.cg 3-stage pipeline (prefetch distance 2), no register staging.
// Stage layout (floats): [0,4096) A slabs (subtile0, subtile1), [4096,6144) B.
#define STAGE_FLOATS 6144
#define STAGE_BYTES  24576

template<int NCHUNK, int FFN1>
__global__ __launch_bounds__(256, 1)
void ffn_mma(const float* __restrict__ Afrag,
             const float* __restrict__ Bfrag,
             const float* __restrict__ bias,
             float* __restrict__ out,
             int out_n) {
    const int e = blockIdx.z;
    const int cnt = g_counts[e];
    const int m0 = blockIdx.y * 256;
    if (m0 >= cnt) return;
    const int off = g_offsets[e];                 // padded, multiple of 128
    const int mt0 = (off >> 7) + blockIdx.y * 2;  // first 128-slab
    int mt1 = mt0 + 1;
    if (mt1 > NMT - 1) mt1 = NMT - 1;             // clamp (pad region only)
    const int nt = blockIdx.x;

    extern __shared__ __align__(16) float smem[];
    const uint32_t sbase = smem_u32(smem);

    const int tid = threadIdx.x;
    const int wid = tid >> 5;
    const int lane = tid & 31;
    const int warp_m = wid >> 1;   // 0..3 (rows warp_m*64 .. +63)
    const int warp_n = wid & 1;    // 0..1
    const int st = warp_m >> 1;    // subtile 0/1
    const int wm = warp_m & 1;     // 0/1 within subtile

    const float* aslab0 = Afrag + (size_t)mt0 * NCHUNK * 2048;
    const float* aslab1 = Afrag + (size_t)mt1 * NCHUNK * 2048;
    const float* bslab = Bfrag + ((size_t)e * gridDim.x + nt) * NCHUNK * 2048;

#define ISSUE(ch, stg) do {                                                    \
    uint32_t sb = sbase + (stg) * STAGE_BYTES;                                 \
    const float* a0 = aslab0 + (size_t)(ch) * 2048;                            \
    const float* a1 = aslab1 + (size_t)(ch) * 2048;                            \
    const float* bb = bslab + (size_t)(ch) * 2048;                             \
    CP16(sb + (tid) * 16,          a0 + (size_t)tid * 4);                      \
    CP16(sb + (tid + 256) * 16,    a0 + (size_t)(tid + 256) * 4);              \
    CP16(sb + (tid + 512) * 16,    a1 + (size_t)tid * 4);                      \
    CP16(sb + (tid + 768) * 16,    a1 + (size_t)(tid + 256) * 4);              \
    CP16(sb + 16384 + (tid) * 16,       bb + (size_t)tid * 4);                 \
    CP16(sb + 16384 + (tid + 256) * 16, bb + (size_t)(tid + 256) * 4);         \
} while (0)

    float c[4][8][4];
#pragma unroll
    for (int mi = 0; mi < 4; mi++)
#pragma unroll
        for (int ni = 0; ni < 8; ni++)
#pragma unroll
            for (int j = 0; j < 4; j++) c[mi][ni][j] = 0.0f;

    // Prologue: prefetch chunks 0 and 1.
    ISSUE(0, 0); CP_COMMIT();
    ISSUE(1, 1); CP_COMMIT();

    int stg = 0;       // stage of current chunk
    for (int ch = 0; ch < NCHUNK; ch++) {
        int nstg = stg + 2; if (nstg >= 3) nstg -= 3;
        if (ch + 2 < NCHUNK) ISSUE(ch + 2, nstg);
        CP_COMMIT();
        CP_WAIT2();
        __syncthreads();

        const float* fap = smem + stg * STAGE_FLOATS + st * 2048;
        const float* fbp = smem + stg * STAGE_FLOATS + 4096;
#pragma unroll
        for (int s = 0; s < 2; s++) {
            uint4 afr[4];
#pragma unroll
            for (int mi = 0; mi < 4; mi++) {
                int mbl = wm * 4 + mi;
                afr[mi] = *(const uint4*)&fap[(mbl * 2 + s) * 128 + lane * 4];
            }
#pragma unroll
            for (int pi = 0; pi < 4; pi++) {
                int pb = warp_n * 4 + pi;
                uint4 bf = *(const uint4*)&fbp[(pb * 2 + s) * 128 + lane * 4];
#pragma unroll
                for (int mi = 0; mi < 4; mi++) {
                    mma_tf32(c[mi][2 * pi + 0], (const uint32_t*)&afr[mi], bf.x, bf.y);
                    mma_tf32(c[mi][2 * pi + 1], (const uint32_t*)&afr[mi], bf.z, bf.w);
                }
            }
        }
        __syncthreads();
        stg = stg + 1; if (stg >= 3) stg -= 3;
    }
#undef ISSUE

    const int g = lane >> 2;
    const int t = lane & 3;
    const int mtile = mt0 + st;   // slab this warp's rows live in

    if (FFN1) {
        // Write h in GEMM2 A-fragment layout (out = g_hf).
        const int n0 = nt * 128;
#pragma unroll
        for (int mi = 0; mi < 4; mi++) {
            const int mbl = wm * 4 + mi;  // fragment block within 128-slab
#pragma unroll
            for (int half = 0; half < 2; half++) {
                int r = warp_m * 64 + mi * 16 + g + half * 8;  // CTA-local row
                if (m0 + r >= cnt) continue;
#pragma unroll
                for (int ni = 0; ni < 8; ni++) {
                    int ch2 = (n0 + warp_n * 64 + ni * 8) >> 4;
                    int s2 = ni & 1;
                    float* blkp = out + (((size_t)mtile * NCH2 + ch2) * 16 + mbl * 2 + s2) * 128;
                    int colb = n0 + warp_n * 64 + ni * 8 + t * 2;
                    float2 bb = *(const float2*)(bias + (size_t)e * F_DIM + colb);
#pragma unroll
                    for (int dx = 0; dx < 2; dx++) {
                        float v = c[mi][ni][half * 2 + dx] + (dx ? bb.y : bb.x);
                        v = to_tf32(gelu_exact(v));
                        int tt = t * 2 + dx;
                        int tloc = tt & 3;
                        int colhalf = tt >> 2;
                        int lane2 = g * 4 + tloc;
                        blkp[lane2 * 4 + half + 2 * colhalf] = v;
                    }
                }
            }
        }
    } else {
        const float* brow = bias + (size_t)e * out_n + nt * 128;
#pragma unroll
        for (int mi = 0; mi < 4; mi++) {
#pragma unroll
            for (int half = 0; half < 2; half++) {
                int r = warp_m * 64 + mi * 16 + g + half * 8;
                int mglob = m0 + r;
                if (mglob >= cnt) continue;
                size_t srow = (size_t)(off + mglob);
                float wt = g_sorted_wt[srow];
                float* orow = out + srow * (size_t)out_n + nt * 128;
#pragma unroll
                for (int ni = 0; ni < 8; ni++) {
                    int col = warp_n * 64 + ni * 8 + t * 2;
                    float2 bb = *(const float2*)(brow + col);
                    float2 o;
                    o.x = wt * (c[mi][ni][half * 2 + 0] + bb.x);
                    o.y = wt * (c[mi][ni][half * 2 + 1] + bb.y);
                    *(float2*)(orow + col) = o;
                }
            }
        }
    }
}

// out[t, d] = y[slot0(t), d] + y[slot1(t), d]
__global__ __launch_bounds__(256) void combine_kernel(float* __restrict__ out) {
    int i = blockIdx.x * 256 + threadIdx.x;
    int t = i >> 10;
    int d = i & 1023;
    int s0 = g_slot[2 * t + 0];
    int s1 = g_slot[2 * t + 1];
    out[i] = g_y[(size_t)s0 * D_DIM + d] + g_y[(size_t)s1 * D_DIM + d];
}

// ---------------------------------------------------------------------------
extern "C" void kernel_launch(void* const* d_in, const int* in_sizes, int n_in,
                              void* d_out, int out_size) {
    const float* x  = (const float*)d_in[0];
    const float* gw = (const float*)d_in[1];
    const float* w1 = (const float*)d_in[2];
    const float* b1 = (const float*)d_in[3];
    const float* w2 = (const float*)d_in[4];
    const float* b2 = (const float*)d_in[5];
    float* out = (float*)d_out;

    float* xa;  cudaGetSymbolAddress((void**)&xa,  g_xa);
    float* hf;  cudaGetSymbolAddress((void**)&hf,  g_hf);
    float* w1f; cudaGetSymbolAddress((void**)&w1f, g_w1f);
    float* w2f; cudaGetSymbolAddress((void**)&w2f, g_w2f);
    float* ybuf; cudaGetSymbolAddress((void**)&ybuf, g_y);

    const int smem_bytes = 3 * STAGE_BYTES;  // 73728
    cudaFuncSetAttribute(ffn_mma<NCH1, 1>,
                         cudaFuncAttributeMaxDynamicSharedMemorySize, smem_bytes);
    cudaFuncSetAttribute(ffn_mma<NCH2, 0>,
                         cudaFuncAttributeMaxDynamicSharedMemorySize, smem_bytes);

    zero_kernel<<<1, 32>>>();
    gate_kernel<<<T_TOK, 256>>>(x, gw);
    scan_kernel<<<1, 32>>>();
    scatter_kernel<<<A_TOT / 256, 256>>>();
    pad_fill_kernel<<<(A_PAD + 255) / 256, 256>>>();

    // Pre-format: weights + gathered activations into fragment slabs.
    wfrag_kernel<<<dim3(NT1, NCH1, E_NUM), 256>>>(w1, w1f, F_DIM);
    wfrag_kernel<<<dim3(NT2, NCH2, E_NUM), 256>>>(w2, w2f, D_DIM);
    xfrag_kernel<<<dim3(NCH1, NMT), 256>>>(x);

    // GEMM1: h = gelu(x @ w1 + b1) -> g_hf (fragment layout)
    ffn_mma<NCH1, 1><<<dim3(NT1, A_TOT / 256, E_NUM), 256, smem_bytes>>>(
        xa, w1f, b1, hf, F_DIM);
    // GEMM2: y = wt * (h @ w2 + b2) -> g_y (row-major)
    ffn_mma<NCH2, 0><<<dim3(NT2, A_TOT / 256, E_NUM), 256, smem_bytes>>>(
        hf, w2f, b2, ybuf, D_DIM);

    combine_kernel<<<(T_TOK * D_DIM) / 256, 256>>>(out);
}

// round 8
// speedup vs baseline: 1.1594x; 1.1594x over previous
#include <cuda_runtime.h>
#include <math.h>
#include <stdint.h>

#define T_TOK 8192
#define D_DIM 1024
#define F_DIM 4096
#define E_NUM 8
#define A_TOT (2 * T_TOK)      /* 16384 real (token, expert) assignments */
#define A_PAD 17408            /* A_TOT + 8*128 padding, multiple of 128 */
#define NMT   (A_PAD / 128)    /* 136 global 128-row M-slabs */
#define NCH1  (D_DIM / 16)     /* 64 K-chunks, GEMM1 */
#define NCH2  (F_DIM / 16)     /* 256 K-chunks, GEMM2 */
#define NT1   (F_DIM / 128)    /* 32 N-tiles, GEMM1 */
#define NT2   (D_DIM / 128)    /* 8 N-tiles, GEMM2 */

// ---------------- scratch (no allocation allowed -> device globals) --------
__device__ int   g_counts[E_NUM];
__device__ int   g_offsets[E_NUM + 1];          // PADDED offsets (mult of 128)
__device__ int   g_expidx[A_TOT];
__device__ int   g_pos[A_TOT];
__device__ float g_wt[A_TOT];
__device__ int   g_slot[A_TOT];
__device__ int   g_sorted_tok[A_PAD];
__device__ float g_sorted_wt[A_PAD];
// Fragment-major buffers: slab = 2048 floats (16 blocks x 32 lanes x 4).
__device__ float g_xa[(size_t)NMT * NCH1 * 2048];           //  68 MB A-frags GEMM1
__device__ float g_hf[(size_t)NMT * NCH2 * 2048];           // 285 MB A-frags GEMM2 (tf32 h)
__device__ float g_w1f[(size_t)E_NUM * NT1 * NCH1 * 2048];  // 128 MB B-frags GEMM1
__device__ float g_w2f[(size_t)E_NUM * NT2 * NCH2 * 2048];  // 128 MB B-frags GEMM2
__device__ float g_y[(size_t)A_PAD * D_DIM];                //  71 MB per-assignment outputs

__device__ __forceinline__ float to_tf32(float v) {
    float r;
    asm("cvt.rna.tf32.f32 %0, %1;" : "=f"(r) : "f"(v));
    return r;
}

__device__ __forceinline__ float gelu_exact(float v) {
    return 0.5f * v * (1.0f + erff(v * 0.70710678118654752440f));
}

// m16n8k8 tf32 mma: C[16x8] += A[16x8] * B[8x8]
__device__ __forceinline__ void mma_tf32(float* c, const uint32_t* a,
                                         uint32_t b0, uint32_t b1) {
    asm volatile(
        "mma.sync.aligned.m16n8k8.row.col.f32.tf32.tf32.f32 "
        "{%0,%1,%2,%3}, {%4,%5,%6,%7}, {%8,%9}, {%0,%1,%2,%3};"
        : "+f"(c[0]), "+f"(c[1]), "+f"(c[2]), "+f"(c[3])
        : "r"(a[0]), "r"(a[1]), "r"(a[2]), "r"(a[3]), "r"(b0), "r"(b1));
}

// ---------------------------------------------------------------------------
__global__ void zero_kernel() {
    if (threadIdx.x < E_NUM) g_counts[threadIdx.x] = 0;
}

__global__ __launch_bounds__(256) void gate_kernel(const float* __restrict__ x,
                                                   const float* __restrict__ gw) {
    __shared__ float red[256][9];
    const int t = blockIdx.x;
    const int tid = threadIdx.x;
    float acc[8] = {0.f, 0.f, 0.f, 0.f, 0.f, 0.f, 0.f, 0.f};
    const float* xr = x + (size_t)t * D_DIM;
    for (int j = tid; j < D_DIM; j += 256) {
        float xv = xr[j];
        const float* g = gw + j * E_NUM;
#pragma unroll
        for (int e = 0; e < 8; e++) acc[e] += xv * g[e];
    }
#pragma unroll
    for (int e = 0; e < 8; e++) red[tid][e] = acc[e];
    __syncthreads();
    for (int s = 128; s > 0; s >>= 1) {
        if (tid < s) {
#pragma unroll
            for (int e = 0; e < 8; e++) red[tid][e] += red[tid + s][e];
        }
        __syncthreads();
    }
    if (tid == 0) {
        float v[8];
#pragma unroll
        for (int e = 0; e < 8; e++) v[e] = red[0][e];
        int i0 = 0;
#pragma unroll
        for (int e = 1; e < 8; e++) if (v[e] > v[i0]) i0 = e;
        int i1 = (i0 == 0) ? 1 : 0;
#pragma unroll
        for (int e = 0; e < 8; e++) if (e != i1 && e != i0 && v[e] > v[i1]) i1 = e;
        float e1 = expf(v[i1] - v[i0]);
        float inv = 1.0f / (1.0f + e1);
        int p0 = atomicAdd(&g_counts[i0], 1);
        int p1 = atomicAdd(&g_counts[i1], 1);
        g_expidx[2 * t + 0] = i0;
        g_expidx[2 * t + 1] = i1;
        g_pos[2 * t + 0] = p0;
        g_pos[2 * t + 1] = p1;
        g_wt[2 * t + 0] = inv;
        g_wt[2 * t + 1] = e1 * inv;
    }
}

__global__ void scan_kernel() {
    if (threadIdx.x == 0) {
        int s = 0;
#pragma unroll
        for (int e = 0; e < E_NUM; e++) {
            g_offsets[e] = s;
            s += (g_counts[e] + 127) & ~127;   // pad each expert to 128
        }
        g_offsets[E_NUM] = s;
    }
}

__global__ void scatter_kernel() {
    int i = blockIdx.x * 256 + threadIdx.x;
    if (i >= A_TOT) return;
    int e = g_expidx[i];
    int s = g_offsets[e] + g_pos[i];
    g_slot[i] = s;
    g_sorted_tok[s] = i >> 1;
    g_sorted_wt[s] = g_wt[i];
}

// Fill padding slots with tok=0, wt=0.
__global__ void pad_fill_kernel() {
    int s = blockIdx.x * 256 + threadIdx.x;
    if (s >= A_PAD) return;
    int e = 0;
#pragma unroll
    for (int i = 1; i < E_NUM; i++) if (s >= g_offsets[i]) e = i;
    int local = s - g_offsets[e];
    if (local >= g_counts[e]) {
        g_sorted_tok[s] = 0;
        g_sorted_wt[s] = 0.0f;
    }
}

// ---------------- fragment pre-format kernels -------------------------------
// Gather routed x rows into A-fragment slabs (tf32-rounded).
__global__ __launch_bounds__(256) void xfrag_kernel(const float* __restrict__ x) {
    const int ch = blockIdx.x;
    const int mt = blockIdx.y;
    __shared__ float sx[128 * 20];
    __shared__ int toks[128];
    const int tid = threadIdx.x;
    if (tid < 128) toks[tid] = g_sorted_tok[mt * 128 + tid];
    __syncthreads();
#pragma unroll
    for (int p = 0; p < 2; p++) {
        int q = tid + p * 256;
        int row = q >> 2, kq = q & 3;
        float4 v = *(const float4*)(x + (size_t)toks[row] * D_DIM + ch * 16 + kq * 4);
        v.x = to_tf32(v.x); v.y = to_tf32(v.y); v.z = to_tf32(v.z); v.w = to_tf32(v.w);
        *(float4*)&sx[row * 20 + kq * 4] = v;
    }
    __syncthreads();
    float* dst = g_xa + ((size_t)mt * NCH1 + ch) * 2048;
#pragma unroll
    for (int p = 0; p < 2; p++) {
        int q = tid + p * 256;
        int blkid = q >> 5, slot = q & 31;
        int mb = blkid >> 1, us = blkid & 1;
        int sg = slot >> 2, t = slot & 3;
        int r0 = mb * 16 + sg, k0 = us * 8 + t;
        float4 v;
        v.x = sx[r0 * 20 + k0];
        v.y = sx[(r0 + 8) * 20 + k0];
        v.z = sx[r0 * 20 + k0 + 4];
        v.w = sx[(r0 + 8) * 20 + k0 + 4];
        *(float4*)&dst[q * 4] = v;
    }
}

// Reformat weights [e][K][N] row-major -> B-fragment slabs (tf32-rounded).
__global__ __launch_bounds__(256) void wfrag_kernel(const float* __restrict__ w,
                                                    float* __restrict__ dstbase,
                                                    int Ndim) {
    const int nt = blockIdx.x;
    const int ch = blockIdx.y;
    const int e = blockIdx.z;
    const int Kdim = gridDim.y * 16;
    __shared__ float s[16 * 132];
    const float* src = w + (size_t)e * Kdim * Ndim + (size_t)(ch * 16) * Ndim + nt * 128;
    const int tid = threadIdx.x;
#pragma unroll
    for (int p = 0; p < 2; p++) {
        int q = tid + p * 256;
        int kk = q >> 5, nn = q & 31;
        float4 v = *(const float4*)(src + (size_t)kk * Ndim + nn * 4);
        v.x = to_tf32(v.x); v.y = to_tf32(v.y); v.z = to_tf32(v.z); v.w = to_tf32(v.w);
        *(float4*)&s[kk * 132 + nn * 4] = v;
    }
    __syncthreads();
    float* dst = dstbase + (((size_t)e * gridDim.x + nt) * gridDim.y + ch) * 2048;
#pragma unroll
    for (int p = 0; p < 2; p++) {
        int q = tid + p * 256;
        int blkid = q >> 5, slot = q & 31;
        int pb = blkid >> 1, us = blkid & 1;
        int sg = slot >> 2, t = slot & 3;
        int n0 = pb * 16 + sg, k0 = us * 8 + t;
        float4 v;
        v.x = s[k0 * 132 + n0];
        v.y = s[(k0 + 4) * 132 + n0];
        v.z = s[k0 * 132 + n0 + 8];
        v.w = s[(k0 + 4) * 132 + n0 + 8];
        *(float4*)&dst[q * 4] = v;
    }
}

// ---------------- mma.sync tf32 grouped GEMM (smem-free) --------------------
// CTA 128x128, 8 warps 4(M)x2(N), warp tile 32x64, 2 CTA/SM = 16 warps/SM.
// Operands are read DIRECTLY from global fragment slabs: a warp's fragment
// load is a lane-contiguous LDG.128. A blocks shared by 2 warps (L1), B by 4
// warps (L1); cross-CTA reuse via L2. No smem, no __syncthreads in mainloop.
template<int NCHUNK, int FFN1>
__global__ __launch_bounds__(256, 2)
void ffn_mma(const float* __restrict__ Afrag,
             const float* __restrict__ Bfrag,
             const float* __restrict__ bias,
             float* __restrict__ out,
             int out_n) {
    const int e = blockIdx.z;
    const int cnt = g_counts[e];
    const int m0 = blockIdx.y * 128;
    if (m0 >= cnt) return;
    const int off = g_offsets[e];              // padded, multiple of 128
    const int mt = (off >> 7) + blockIdx.y;    // global M-tile index
    const int nt = blockIdx.x;

    const int tid = threadIdx.x;
    const int wid = tid >> 5;
    const int lane = tid & 31;
    const int warp_m = wid >> 1;   // 0..3
    const int warp_n = wid & 1;    // 0..1

    // Per-warp fragment base pointers (block = frag*2 + s, 128 floats each).
    const float* ab = Afrag + (size_t)mt * NCHUNK * 2048
                    + (warp_m * 4) * 128 + lane * 4;
    const float* bb = Bfrag + ((size_t)e * gridDim.x + nt) * NCHUNK * 2048
                    + (warp_n * 8) * 128 + lane * 4;

    float c[2][8][4];
#pragma unroll
    for (int mi = 0; mi < 2; mi++)
#pragma unroll
        for (int ni = 0; ni < 8; ni++)
#pragma unroll
            for (int j = 0; j < 4; j++) c[mi][ni][j] = 0.0f;

#pragma unroll 2
    for (int ch = 0; ch < NCHUNK; ch++) {
        const float* ap = ab + (size_t)ch * 2048;
        const float* bp = bb + (size_t)ch * 2048;
#pragma unroll
        for (int s = 0; s < 2; s++) {
            uint4 av[2];
            uint4 bv[4];
#pragma unroll
            for (int mi = 0; mi < 2; mi++)
                av[mi] = *(const uint4*)(ap + (mi * 2 + s) * 128);
#pragma unroll
            for (int pi = 0; pi < 4; pi++)
                bv[pi] = *(const uint4*)(bp + (pi * 2 + s) * 128);
#pragma unroll
            for (int pi = 0; pi < 4; pi++)
#pragma unroll
                for (int mi = 0; mi < 2; mi++) {
                    mma_tf32(c[mi][2 * pi + 0], (const uint32_t*)&av[mi], bv[pi].x, bv[pi].y);
                    mma_tf32(c[mi][2 * pi + 1], (const uint32_t*)&av[mi], bv[pi].z, bv[pi].w);
                }
        }
    }

    const int g = lane >> 2;
    const int t = lane & 3;

    if (FFN1) {
        // Write h in GEMM2 A-fragment layout (out = g_hf).
        const int n0 = nt * 128;
#pragma unroll
        for (int mi = 0; mi < 2; mi++) {
            const int mb = warp_m * 2 + mi;
#pragma unroll
            for (int half = 0; half < 2; half++) {
                int r = warp_m * 32 + mi * 16 + g + half * 8;
                if (m0 + r >= cnt) continue;
#pragma unroll
                for (int ni = 0; ni < 8; ni++) {
                    int ch2 = (n0 + warp_n * 64 + ni * 8) >> 4;
                    int s2 = ni & 1;
                    float* blkp = out + (((size_t)mt * NCH2 + ch2) * 16 + mb * 2 + s2) * 128;
                    int colb = n0 + warp_n * 64 + ni * 8 + t * 2;
                    float2 bb2 = *(const float2*)(bias + (size_t)e * F_DIM + colb);
#pragma unroll
                    for (int dx = 0; dx < 2; dx++) {
                        float v = c[mi][ni][half * 2 + dx] + (dx ? bb2.y : bb2.x);
                        v = to_tf32(gelu_exact(v));
                        int tt = t * 2 + dx;
                        int tloc = tt & 3;
                        int colhalf = tt >> 2;
                        int lane2 = g * 4 + tloc;
                        blkp[lane2 * 4 + half + 2 * colhalf] = v;
                    }
                }
            }
        }
    } else {
        const float* brow = bias + (size_t)e * out_n + nt * 128;
#pragma unroll
        for (int mi = 0; mi < 2; mi++) {
#pragma unroll
            for (int half = 0; half < 2; half++) {
                int r = warp_m * 32 + mi * 16 + g + half * 8;
                int mglob = m0 + r;
                if (mglob >= cnt) continue;
                size_t srow = (size_t)(off + mglob);
                float wt = g_sorted_wt[srow];
                float* orow = out + srow * (size_t)out_n + nt * 128;
#pragma unroll
                for (int ni = 0; ni < 8; ni++) {
                    int col = warp_n * 64 + ni * 8 + t * 2;
                    float2 bb2 = *(const float2*)(brow + col);
                    float2 o;
                    o.x = wt * (c[mi][ni][half * 2 + 0] + bb2.x);
                    o.y = wt * (c[mi][ni][half * 2 + 1] + bb2.y);
                    *(float2*)(orow + col) = o;
                }
            }
        }
    }
}

// out[t, d] = y[slot0(t), d] + y[slot1(t), d]
__global__ __launch_bounds__(256) void combine_kernel(float* __restrict__ out) {
    int i = blockIdx.x * 256 + threadIdx.x;
    int t = i >> 10;
    int d = i & 1023;
    int s0 = g_slot[2 * t + 0];
    int s1 = g_slot[2 * t + 1];
    out[i] = g_y[(size_t)s0 * D_DIM + d] + g_y[(size_t)s1 * D_DIM + d];
}

// ---------------------------------------------------------------------------
extern "C" void kernel_launch(void* const* d_in, const int* in_sizes, int n_in,
                              void* d_out, int out_size) {
    const float* x  = (const float*)d_in[0];
    const float* gw = (const float*)d_in[1];
    const float* w1 = (const float*)d_in[2];
    const float* b1 = (const float*)d_in[3];
    const float* w2 = (const float*)d_in[4];
    const float* b2 = (const float*)d_in[5];
    float* out = (float*)d_out;

    float* xa;  cudaGetSymbolAddress((void**)&xa,  g_xa);
    float* hf;  cudaGetSymbolAddress((void**)&hf,  g_hf);
    float* w1f; cudaGetSymbolAddress((void**)&w1f, g_w1f);
    float* w2f; cudaGetSymbolAddress((void**)&w2f, g_w2f);
    float* ybuf; cudaGetSymbolAddress((void**)&ybuf, g_y);

    zero_kernel<<<1, 32>>>();
    gate_kernel<<<T_TOK, 256>>>(x, gw);
    scan_kernel<<<1, 32>>>();
    scatter_kernel<<<A_TOT / 256, 256>>>();
    pad_fill_kernel<<<(A_PAD + 255) / 256, 256>>>();

    // Pre-format: weights + gathered activations into fragment slabs.
    wfrag_kernel<<<dim3(NT1, NCH1, E_NUM), 256>>>(w1, w1f, F_DIM);
    wfrag_kernel<<<dim3(NT2, NCH2, E_NUM), 256>>>(w2, w2f, D_DIM);
    xfrag_kernel<<<dim3(NCH1, NMT), 256>>>(x);

    // GEMM1: h = gelu(x @ w1 + b1) -> g_hf (fragment layout)
    ffn_mma<NCH1, 1><<<dim3(NT1, A_TOT / 128, E_NUM), 256>>>(
        xa, w1f, b1, hf, F_DIM);
    // GEMM2: y = wt * (h @ w2 + b2) -> g_y (row-major)
    ffn_mma<NCH2, 0><<<dim3(NT2, A_TOT / 128, E_NUM), 256>>>(
        hf, w2f, b2, ybuf, D_DIM);

    combine_kernel<<<(T_TOK * D_DIM) / 256, 256>>>(out);
}